// round 17
// baseline (speedup 1.0000x reference)
#include <cuda_runtime.h>
#include <math.h>
#include <stdint.h>

// ---------------------------------------------------------------------------
// SearchNet: cosine similarity (1 query x N database rows) + top-k
//   out[0..k-1]  = top-k values (desc, ties -> lower index first)
//   out[k..2k-1] = top-k indices (as float)
//
// Pipeline (4 kernels):
//   k_init        : normalize query, zero 64K-bin histogram + counters
//   k_sims        : 1 GB stream (4 rows/warp); sims + fused 16-bit histogram
//   k_scan        : suffix-scan 65536 bins -> 16-bit threshold
//   k_gather_final: float4 gather of survivors; last block rank-selects
// ---------------------------------------------------------------------------

#define DIMS        512
#define MAXN        500000
#define HBINS       65536
#define CAP         4096
#define EPSF        1e-8f

__device__ float    g_qn[DIMS];
__device__ float    g_sims[MAXN];
__device__ int      g_hist[HBINS];
__device__ int      g_counter;
__device__ int      g_done;
__device__ unsigned g_thresh;     // select all keys >= g_thresh
__device__ unsigned g_candKey[CAP];
__device__ int      g_candIdx[CAP];
__device__ float    g_candVal[CAP];

__device__ __forceinline__ unsigned mono(float f) {
    unsigned u = __float_as_uint(f);
    return (u & 0x80000000u) ? ~u : (u | 0x80000000u);
}

// ---- K1: normalize query, zero scratch (64 blocks) --------------------------
__global__ void __launch_bounds__(512) k_init(const float* __restrict__ q, int D) {
    for (int i = blockIdx.x * 512 + threadIdx.x; i < HBINS; i += gridDim.x * 512)
        g_hist[i] = 0;

    if (blockIdx.x != 0) return;
    __shared__ float red[512];
    int t = threadIdx.x;
    float v = (t < D) ? q[t] : 0.0f;
    red[t] = v * v;
    __syncthreads();
    #pragma unroll
    for (int s = 256; s > 0; s >>= 1) {
        if (t < s) red[t] += red[t + s];
        __syncthreads();
    }
    float inv = 1.0f / fmaxf(sqrtf(red[0]), EPSF);
    if (t < D) g_qn[t] = v * inv;
    if (t == 0) { g_counter = 0; g_done = 0; g_thresh = 0; }
}

// ---- K2: 1 GB streaming pass (FOUR rows per warp, MLP_p1 = 16) --------------
__global__ void __launch_bounds__(512) k_sims(const float* __restrict__ db, int N) {
    __shared__ float4 qs[DIMS / 4];
    int t = threadIdx.x;
    if (t < DIMS / 4) qs[t] = reinterpret_cast<const float4*>(g_qn)[t];
    __syncthreads();

    int warp = (blockIdx.x * 512 + t) >> 5;
    int lane = t & 31;
    int r0   = warp * 4;
    if (r0 >= N) return;

    const float4* base = reinterpret_cast<const float4*>(db) + (size_t)r0 * (DIMS / 4);

    float4 v[4][4];
    if (r0 + 3 < N) {
        #pragma unroll
        for (int r = 0; r < 4; r++)
            #pragma unroll
            for (int i = 0; i < 4; i++)
                v[r][i] = __ldcs(&base[r * (DIMS / 4) + lane + 32 * i]);
    } else {
        #pragma unroll
        for (int r = 0; r < 4; r++)
            #pragma unroll
            for (int i = 0; i < 4; i++)
                v[r][i] = (r0 + r < N) ? __ldcs(&base[r * (DIMS / 4) + lane + 32 * i])
                                       : make_float4(0.f, 0.f, 0.f, 0.f);
    }

    float dt[4] = {0.f, 0.f, 0.f, 0.f};
    float nr[4] = {0.f, 0.f, 0.f, 0.f};
    #pragma unroll
    for (int i = 0; i < 4; i++) {
        float4 q = qs[lane + 32 * i];
        #pragma unroll
        for (int r = 0; r < 4; r++) {
            float4 a = v[r][i];
            dt[r] += a.x * q.x + a.y * q.y + a.z * q.z + a.w * q.w;
            nr[r] += a.x * a.x + a.y * a.y + a.z * a.z + a.w * a.w;
        }
    }
    #pragma unroll
    for (int o = 16; o > 0; o >>= 1) {
        #pragma unroll
        for (int r = 0; r < 4; r++) {
            dt[r] += __shfl_down_sync(0xffffffffu, dt[r], o);
            nr[r] += __shfl_down_sync(0xffffffffu, nr[r], o);
        }
    }
    if (lane == 0) {
        #pragma unroll
        for (int r = 0; r < 4; r++) {
            if (r0 + r < N) {
                float s = dt[r] / fmaxf(sqrtf(nr[r]), EPSF);
                g_sims[r0 + r] = s;
                atomicAdd(&g_hist[mono(s) >> 16], 1);
            }
        }
    }
}

// ---- K3: parallel suffix-scan of 65536 bins (1 block, 1024 threads) ---------
__global__ void __launch_bounds__(1024) k_scan(const int* topk) {
    __shared__ int warpTot[32];
    __shared__ int warpSfx[33];

    int k = topk ? *topk : 100;
    if (k < 1) k = 1;

    int t    = threadIdx.x;
    int lane = t & 31;
    int w    = t >> 5;

    const int4* h4 = reinterpret_cast<const int4*>(g_hist);
    int local = 0;
    #pragma unroll
    for (int i = 0; i < 16; i++) {
        int4 v = h4[t * 16 + i];
        local += v.x + v.y + v.z + v.w;
    }

    int s = local;
    #pragma unroll
    for (int o = 1; o < 32; o <<= 1) {
        int u = __shfl_down_sync(0xffffffffu, s, o);
        if (lane + o < 32) s += u;
    }
    if (lane == 0) warpTot[w] = s;
    __syncthreads();

    if (w == 0) {
        int ws = warpTot[lane];
        #pragma unroll
        for (int o = 1; o < 32; o <<= 1) {
            int u = __shfl_down_sync(0xffffffffu, ws, o);
            if (lane + o < 32) ws += u;
        }
        warpSfx[lane] = ws;
        if (lane == 0) warpSfx[32] = 0;
    }
    __syncthreads();

    int above = (s - local) + warpSfx[w + 1];

    if (above < k && above + local >= k) {
        int cum = above;
        for (int j = 63; j >= 0; --j) {
            cum += g_hist[t * 64 + j];
            if (cum >= k) {
                g_thresh = ((unsigned)(t * 64 + j)) << 16;
                break;
            }
        }
    }
}

// ---- K4: float4 gather of survivors; last block rank-selects ----------------
__global__ void __launch_bounds__(256) k_gather_final(int N, const int* topk,
                                                      float* __restrict__ out,
                                                      int out_size) {
    unsigned th = g_thresh;
    int n4 = N >> 2;
    const float4* s4 = reinterpret_cast<const float4*>(g_sims);
    int gtid  = blockIdx.x * 256 + threadIdx.x;
    int gstep = gridDim.x * 256;

    for (int i = gtid; i < n4; i += gstep) {
        float4 v = s4[i];
        unsigned k0 = mono(v.x), k1 = mono(v.y), k2 = mono(v.z), k3 = mono(v.w);
        if (k0 >= th) { int p = atomicAdd(&g_counter, 1); if (p < CAP) { g_candKey[p] = k0; g_candIdx[p] = 4*i;   g_candVal[p] = v.x; } }
        if (k1 >= th) { int p = atomicAdd(&g_counter, 1); if (p < CAP) { g_candKey[p] = k1; g_candIdx[p] = 4*i+1; g_candVal[p] = v.y; } }
        if (k2 >= th) { int p = atomicAdd(&g_counter, 1); if (p < CAP) { g_candKey[p] = k2; g_candIdx[p] = 4*i+2; g_candVal[p] = v.z; } }
        if (k3 >= th) { int p = atomicAdd(&g_counter, 1); if (p < CAP) { g_candKey[p] = k3; g_candIdx[p] = 4*i+3; g_candVal[p] = v.w; } }
    }
    // scalar tail (N not divisible by 4)
    for (int i = (n4 << 2) + gtid; i < N; i += gstep) {
        float v = g_sims[i];
        unsigned key = mono(v);
        if (key >= th) {
            int p = atomicAdd(&g_counter, 1);
            if (p < CAP) { g_candKey[p] = key; g_candIdx[p] = i; g_candVal[p] = v; }
        }
    }

    // last-block-done: final block performs the exact k-selection
    __shared__ int s_last;
    __threadfence();
    __syncthreads();
    if (threadIdx.x == 0)
        s_last = (atomicAdd(&g_done, 1) == (int)gridDim.x - 1);
    __syncthreads();
    if (!s_last) return;

    __shared__ unsigned sk[CAP];
    __shared__ int      si[CAP];
    int n = g_counter;
    if (n > CAP) n = CAP;
    int k = topk ? *topk : 100;

    for (int i = threadIdx.x; i < n; i += 256) {
        sk[i] = g_candKey[i];
        si[i] = g_candIdx[i];
    }
    __syncthreads();

    for (int i = threadIdx.x; i < n; i += 256) {
        unsigned mk = sk[i];
        int      mi = si[i];
        int r = 0;
        for (int j = 0; j < n; j++) {
            unsigned kj = sk[j];
            r += (kj > mk) || (kj == mk && si[j] < mi);
        }
        if (r < k) {
            if (r < out_size)     out[r]     = g_candVal[i];
            if (k + r < out_size) out[k + r] = (float)si[i];
        }
    }
}

// ---------------------------------------------------------------------------
extern "C" void kernel_launch(void* const* d_in, const int* in_sizes, int n_in,
                              void* d_out, int out_size) {
    const float* q    = (const float*)d_in[0];
    const float* db   = (const float*)d_in[1];
    const int*   topk = (n_in >= 3) ? (const int*)d_in[2] : nullptr;

    int D = in_sizes[0];               // 512
    int N = in_sizes[1] / D;           // 500000
    if (N > MAXN) N = MAXN;

    k_init<<<64, 512>>>(q, D);

    // 4 rows per warp, 16 warps per block -> 64 rows per block
    int blocks = (N + 63) / 64;
    k_sims<<<blocks, 512>>>(db, N);

    k_scan<<<1, 1024>>>(topk);
    k_gather_final<<<256, 256>>>(N, topk, (float*)d_out, out_size);
}